// round 10
// baseline (speedup 1.0000x reference)
#include <cuda_runtime.h>
#include <cuda_fp16.h>
#include <cstdint>

#define Bv   2
#define Hv   16
#define Sv   2048
#define DKv  64
#define BHv  32
#define BM   64
#define BN   64
#define NITER (Sv/BN)
#define SCALE2 0.18033688011112042f   // (1/8)*log2(e)

#define NELEM ((size_t)BHv * Sv * DKv)      // 4,194,304
#define NMASKW ((size_t)Bv * Sv * Sv / 32)  // 262,144 uint32

__device__ __align__(16) __half g_Qa[NELEM];
__device__ __align__(16) __half g_Qb[NELEM];
__device__ __align__(16) __half g_Ka[NELEM];
__device__ __align__(16) __half g_Kb[NELEM];
__device__ __align__(16) __half g_Vh[NELEM];
__device__ __align__(16) uint32_t g_Mb[NMASKW];

__device__ __forceinline__ uint32_t smem_u32(const void* p) {
    uint32_t a;
    asm("{ .reg .u64 t; cvta.to.shared.u64 t, %1; cvt.u32.u64 %0, t; }" : "=r"(a) : "l"(p));
    return a;
}
__device__ __forceinline__ void mma16816(float* d, const uint32_t* a, uint32_t b0, uint32_t b1) {
    asm volatile("mma.sync.aligned.m16n8k16.row.col.f32.f16.f16.f32 "
        "{%0,%1,%2,%3}, {%4,%5,%6,%7}, {%8,%9}, {%0,%1,%2,%3};"
        : "+f"(d[0]), "+f"(d[1]), "+f"(d[2]), "+f"(d[3])
        : "r"(a[0]), "r"(a[1]), "r"(a[2]), "r"(a[3]), "r"(b0), "r"(b1));
}
__device__ __forceinline__ void ldsm4(uint32_t& a, uint32_t& b, uint32_t& c, uint32_t& d, uint32_t addr) {
    asm volatile("ldmatrix.sync.aligned.m8n8.x4.shared.b16 {%0,%1,%2,%3}, [%4];"
                 : "=r"(a), "=r"(b), "=r"(c), "=r"(d) : "r"(addr));
}
__device__ __forceinline__ void ldsm4t(uint32_t& a, uint32_t& b, uint32_t& c, uint32_t& d, uint32_t addr) {
    asm volatile("ldmatrix.sync.aligned.m8n8.x4.trans.shared.b16 {%0,%1,%2,%3}, [%4];"
                 : "=r"(a), "=r"(b), "=r"(c), "=r"(d) : "r"(addr));
}
__device__ __forceinline__ uint32_t pack_h(float hi, float lo) {
    uint32_t r;
    asm("cvt.rn.f16x2.f32 %0, %1, %2;" : "=r"(r) : "f"(hi), "f"(lo));
    return r;
}
#define CPA(dst, src) asm volatile("cp.async.cg.shared.global [%0], [%1], 16;" :: "r"(dst), "l"(src) : "memory")

// u is already scale*log2e*dot (Q pre-scaled). p = (m && u>0) ? 2^u : 0.
// MUFU ex2 (rt=8/SMSP, ~14us total chip budget) instead of 11-instr FMA poly.
__device__ __forceinline__ float pexpb(float u, unsigned m) {
    float e;
    asm("ex2.approx.ftz.f32 %0, %1;" : "=f"(e) : "f"(u));
    return ((u > 0.0f) && (m != 0u)) ? e : 0.0f;
}

// ---- prep: Q (pre-scaled) and K 2-way split; V single fp16; K/V chunk-swizzled ----
__global__ __launch_bounds__(256) void prep(const float* __restrict__ Q,
                                            const float* __restrict__ K,
                                            const float* __restrict__ V) {
    const uint32_t g = blockIdx.x * 256 + threadIdx.x;   // 16B-chunk index (8 halves)
    const uint32_t s = (g >> 3) & (Sv - 1);
    const int which = blockIdx.y;                         // 0:Q 1:K 2:V
    const float* src = which == 0 ? Q : which == 1 ? K : V;
    const float4 v0 = ((const float4*)src)[g * 2 + 0];
    const float4 v1 = ((const float4*)src)[g * 2 + 1];
    float x[8] = {v0.x, v0.y, v0.z, v0.w, v1.x, v1.y, v1.z, v1.w};
    if (which == 0) {
#pragma unroll
        for (int e = 0; e < 8; e++) x[e] *= SCALE2;       // fold scale*log2e into Q
    }
    const uint32_t og = (which == 0) ? g : ((g & ~7u) | ((g & 7u) ^ (s & 7u)));

    uint4 ua, ub;
    __half* A = (__half*)&ua;
    __half* B = (__half*)&ub;
#pragma unroll
    for (int e = 0; e < 8; e++) {
        __half a = __float2half_rn(x[e]);
        A[e] = a;
        B[e] = __float2half_rn(x[e] - __half2float(a));
    }
    if (which == 0)      { ((uint4*)g_Qa)[og] = ua; ((uint4*)g_Qb)[og] = ub; }
    else if (which == 1) { ((uint4*)g_Ka)[og] = ua; ((uint4*)g_Kb)[og] = ub; }
    else                 { ((uint4*)g_Vh)[og] = ua; }
}

// ---- prep: pack mask floats (0.0/1.0) into bits, 32 keys per uint32 ----
__global__ __launch_bounds__(256) void prep_mask(const float* __restrict__ M) {
    const uint32_t w = blockIdx.x * 256 + threadIdx.x;
    const float4* src = (const float4*)M + (size_t)w * 8;
    uint32_t bits = 0;
#pragma unroll
    for (int i = 0; i < 8; i++) {
        float4 v = src[i];
        bits |= (v.x != 0.0f ? 1u : 0u) << (4 * i + 0);
        bits |= (v.y != 0.0f ? 1u : 0u) << (4 * i + 1);
        bits |= (v.z != 0.0f ? 1u : 0u) << (4 * i + 2);
        bits |= (v.w != 0.0f ? 1u : 0u) << (4 * i + 3);
    }
    g_Mb[w] = bits;
}

// ---- main: register-MMA flash attention, 4 MMA products, bitmask, 3 buffers ----
__global__ __launch_bounds__(128, 3)
void sdp_mma(float* __restrict__ Out) {
    extern __shared__ char smem[];
    const uint32_t sbase = smem_u32(smem);

    const int tid  = threadIdx.x;
    const int lane = tid & 31, warp = tid >> 5;
    const int bh = blockIdx.y, q0 = blockIdx.x * BM, b = bh >> 4;
    const int lq  = lane >> 2;
    const int lc2 = (lane & 3) * 2;
    const int r1 = q0 + warp * 16 + lq, r2 = r1 + 8;

    // Q fragments (2 splits), loaded once
    uint32_t qf[2][4][4];
    {
        const __half* qs[2] = {g_Qa, g_Qb};
#pragma unroll
        for (int sp = 0; sp < 2; sp++)
#pragma unroll
            for (int c = 0; c < 4; c++)
#pragma unroll
                for (int r = 0; r < 4; r++) {
                    int m = (r & 1) ? r2 : r1;
                    int k = c * 16 + ((r >> 1) << 3) + lc2;
                    qf[sp][c][r] = *(const uint32_t*)(qs[sp] + ((size_t)bh * Sv + m) * DKv + k);
                }
    }

    float O[8][4];
#pragma unroll
    for (int j = 0; j < 8; j++)
#pragma unroll
        for (int e = 0; e < 4; e++) O[j][e] = 0.0f;
    float lacc0 = 0.0f, lacc1 = 0.0f;

    const uint64_t* mb1 = (const uint64_t*)g_Mb + (((size_t)b * Sv + r1) << 5);
    const uint64_t* mb2 = (const uint64_t*)g_Mb + (((size_t)b * Sv + r2) << 5);

    const size_t gbyte0 = (size_t)(bh * Sv) * 128;
    const char* garr[3] = {(const char*)g_Ka + gbyte0, (const char*)g_Kb + gbyte0,
                           (const char*)g_Vh + gbyte0};

    // prologue: tiles 0 and 1 into buffers 0 and 1
#pragma unroll
    for (int a = 0; a < 3; a++)
#pragma unroll
        for (int i = 0; i < 4; i++) {
            uint32_t off = (uint32_t)(tid + i * 128) * 16;
            CPA(sbase + a * 8192 + off, garr[a] + off);
        }
    asm volatile("cp.async.commit_group;" ::: "memory");
#pragma unroll
    for (int a = 0; a < 3; a++)
#pragma unroll
        for (int i = 0; i < 4; i++) {
            uint32_t off = (uint32_t)(tid + i * 128) * 16;
            CPA(sbase + 24576 + a * 8192 + off, garr[a] + 8192 + off);
        }
    asm volatile("cp.async.commit_group;" ::: "memory");

    int cur = 0, pf = 2;
    for (int t = 0; t < NITER; t++) {
        // mask words early — QK MMAs below hide the L2 latency
        const uint64_t s1 = mb1[t] >> lc2;
        const uint64_t s2 = mb2[t] >> lc2;

        if (t == NITER - 1) asm volatile("cp.async.wait_group 0;" ::: "memory");
        else                asm volatile("cp.async.wait_group 1;" ::: "memory");
        __syncthreads();   // tile t ready; all warps done with the buffer being refilled

        if (t + 2 < NITER) {
            const uint32_t sb = sbase + pf * 24576;
            const size_t go = (size_t)(t + 2) * 8192;
#pragma unroll
            for (int a = 0; a < 3; a++)
#pragma unroll
                for (int i = 0; i < 4; i++) {
                    uint32_t off = (uint32_t)(tid + i * 128) * 16;
                    CPA(sb + a * 8192 + off, garr[a] + go + off);
                }
            asm volatile("cp.async.commit_group;" ::: "memory");
        }

        const uint32_t sK = sbase + cur * 24576;   // Ka @ +0, Kb @ +8192
        const uint32_t sV = sK + 16384;            // Vh

        // ---- S = Q K^T via 3 split products ----
        float S[8][4];
#pragma unroll
        for (int j = 0; j < 8; j++)
#pragma unroll
            for (int e = 0; e < 4; e++) S[j][e] = 0.0f;

        const int rowk = lane & 7;
        const int half = (lane >> 3) & 1;
        const uint32_t karr = (uint32_t)(lane >> 4) * 8192;
#pragma unroll
        for (int c = 0; c < 4; c++) {
            const int chk = 2 * c + half;
#pragma unroll
            for (int j = 0; j < 8; j++) {
                const int row = 8 * j + rowk;
                const uint32_t off = karr + (uint32_t)row * 128 + (uint32_t)((chk ^ (row & 7)) << 4);
                uint32_t ka0, ka1, kb0, kb1;
                ldsm4(ka0, ka1, kb0, kb1, sK + off);
                mma16816(S[j], qf[0][c], ka0, ka1);
                mma16816(S[j], qf[1][c], ka0, ka1);
                mma16816(S[j], qf[0][c], kb0, kb1);
            }
        }

        // ---- masked softmax via bit tests + MUFU ex2 ----
        uint32_t aph[8][2];
#pragma unroll
        for (int f = 0; f < 8; f++) {
            const unsigned w1 = (unsigned)(s1 >> (8 * f));
            const unsigned w2 = (unsigned)(s2 >> (8 * f));
            float p0 = pexpb(S[f][0], w1 & 1u);
            float p1 = pexpb(S[f][1], w1 & 2u);
            float p2 = pexpb(S[f][2], w2 & 1u);
            float p3 = pexpb(S[f][3], w2 & 2u);
            lacc0 += p0 + p1;
            lacc1 += p2 + p3;
            aph[f][0] = pack_h(p1, p0);
            aph[f][1] = pack_h(p3, p2);
        }

        // ---- O += P V, single product ----
        const int rowv16 = lane & 15;
        const uint32_t jsel = (uint32_t)(lane >> 4);
#pragma unroll
        for (int c = 0; c < 4; c++) {
            uint32_t a_h[4] = {aph[2 * c][0], aph[2 * c][1], aph[2 * c + 1][0], aph[2 * c + 1][1]};
            const int rowv = 16 * c + rowv16;
#pragma unroll
            for (int jj = 0; jj < 4; jj++) {
                const uint32_t j0 = 2 * jj;
                const uint32_t offv = (uint32_t)rowv * 128 + (uint32_t)(((j0 + jsel) ^ (rowv & 7)) << 4);
                uint32_t v00, v01, v10, v11;
                ldsm4t(v00, v01, v10, v11, sV + offv);
                mma16816(O[j0],     a_h, v00, v01);
                mma16816(O[j0 + 1], a_h, v10, v11);
            }
        }

        cur = (cur == 2) ? 0 : cur + 1;
        pf  = (pf  == 2) ? 0 : pf  + 1;
    }

    // ---- epilogue ----
    lacc0 += __shfl_xor_sync(0xffffffffu, lacc0, 1);
    lacc0 += __shfl_xor_sync(0xffffffffu, lacc0, 2);
    lacc1 += __shfl_xor_sync(0xffffffffu, lacc1, 1);
    lacc1 += __shfl_xor_sync(0xffffffffu, lacc1, 2);
    const float li1 = 1.0f / lacc0;
    const float li2 = 1.0f / lacc1;

    float* o1 = Out + ((size_t)bh * Sv + r1) * DKv + lc2;
    float* o2 = Out + ((size_t)bh * Sv + r2) * DKv + lc2;
#pragma unroll
    for (int j = 0; j < 8; j++) {
        float2 w1 = make_float2(O[j][0] * li1, O[j][1] * li1);
        float2 w2 = make_float2(O[j][2] * li2, O[j][3] * li2);
        *(float2*)(o1 + 8 * j) = w1;
        *(float2*)(o2 + 8 * j) = w2;
    }
}

extern "C" void kernel_launch(void* const* d_in, const int* in_sizes, int n_in,
                              void* d_out, int out_size) {
    const float* Q = (const float*)d_in[0];
    const float* K = (const float*)d_in[1];
    const float* V = (const float*)d_in[2];
    const float* M = (const float*)d_in[3];
    float* Out = (float*)d_out;

    prep<<<dim3((unsigned)(NELEM / 8 / 256), 3), 256>>>(Q, K, V);
    prep_mask<<<(unsigned)(NMASKW / 256), 256>>>(M);

    cudaFuncSetAttribute(sdp_mma, cudaFuncAttributeMaxDynamicSharedMemorySize, 73728);
    sdp_mma<<<dim3(Sv / BM, BHv), 128, 73728>>>(Out);
}

// round 11
// speedup vs baseline: 1.5072x; 1.5072x over previous
#include <cuda_runtime.h>
#include <cuda_fp16.h>
#include <cstdint>

#define Bv   2
#define Hv   16
#define Sv   2048
#define DKv  64
#define BHv  32
#define BM   64
#define BN   64
#define NITER (Sv/BN)
#define SCALE2 0.18033688011112042f   // (1/8)*log2(e)

#define NELEM ((size_t)BHv * Sv * DKv)      // 4,194,304
#define NMASKW ((size_t)Bv * Sv * Sv / 32)  // 262,144 uint32

__device__ __align__(16) __half g_Qa[NELEM];
__device__ __align__(16) __half g_Qb[NELEM];
__device__ __align__(16) __half g_Ka[NELEM];
__device__ __align__(16) __half g_Kb[NELEM];
__device__ __align__(16) __half g_Vh[NELEM];
__device__ __align__(16) uint32_t g_Mb[NMASKW];

__device__ __forceinline__ uint32_t smem_u32(const void* p) {
    uint32_t a;
    asm("{ .reg .u64 t; cvta.to.shared.u64 t, %1; cvt.u32.u64 %0, t; }" : "=r"(a) : "l"(p));
    return a;
}
__device__ __forceinline__ void mma16816(float* d, const uint32_t* a, uint32_t b0, uint32_t b1) {
    asm volatile("mma.sync.aligned.m16n8k16.row.col.f32.f16.f16.f32 "
        "{%0,%1,%2,%3}, {%4,%5,%6,%7}, {%8,%9}, {%0,%1,%2,%3};"
        : "+f"(d[0]), "+f"(d[1]), "+f"(d[2]), "+f"(d[3])
        : "r"(a[0]), "r"(a[1]), "r"(a[2]), "r"(a[3]), "r"(b0), "r"(b1));
}
__device__ __forceinline__ void ldsm4(uint32_t& a, uint32_t& b, uint32_t& c, uint32_t& d, uint32_t addr) {
    asm volatile("ldmatrix.sync.aligned.m8n8.x4.shared.b16 {%0,%1,%2,%3}, [%4];"
                 : "=r"(a), "=r"(b), "=r"(c), "=r"(d) : "r"(addr));
}
__device__ __forceinline__ void ldsm4t(uint32_t& a, uint32_t& b, uint32_t& c, uint32_t& d, uint32_t addr) {
    asm volatile("ldmatrix.sync.aligned.m8n8.x4.trans.shared.b16 {%0,%1,%2,%3}, [%4];"
                 : "=r"(a), "=r"(b), "=r"(c), "=r"(d) : "r"(addr));
}
__device__ __forceinline__ uint32_t pack_h(float hi, float lo) {
    uint32_t r;
    asm("cvt.rn.f16x2.f32 %0, %1, %2;" : "=r"(r) : "f"(hi), "f"(lo));
    return r;
}
#define CPA(dst, src) asm volatile("cp.async.cg.shared.global [%0], [%1], 16;" :: "r"(dst), "l"(src) : "memory")

// u is already scale*log2e*dot (Q pre-scaled). p = (m && u>0) ? 2^u : 0.
__device__ __forceinline__ float pexpb(float u, unsigned m) {
    float e;
    asm("ex2.approx.ftz.f32 %0, %1;" : "=f"(e) : "f"(u));
    return ((u > 0.0f) && (m != 0u)) ? e : 0.0f;
}

// ---- prep: Q (pre-scaled) and K 2-way split; V single fp16; K/V chunk-swizzled ----
__global__ __launch_bounds__(256) void prep(const float* __restrict__ Q,
                                            const float* __restrict__ K,
                                            const float* __restrict__ V) {
    const uint32_t g = blockIdx.x * 256 + threadIdx.x;   // 16B-chunk index (8 halves)
    const uint32_t s = (g >> 3) & (Sv - 1);
    const int which = blockIdx.y;                         // 0:Q 1:K 2:V
    const float* src = which == 0 ? Q : which == 1 ? K : V;
    const float4 v0 = ((const float4*)src)[g * 2 + 0];
    const float4 v1 = ((const float4*)src)[g * 2 + 1];
    float x[8] = {v0.x, v0.y, v0.z, v0.w, v1.x, v1.y, v1.z, v1.w};
    if (which == 0) {
#pragma unroll
        for (int e = 0; e < 8; e++) x[e] *= SCALE2;       // fold scale*log2e into Q
    }
    const uint32_t og = (which == 0) ? g : ((g & ~7u) | ((g & 7u) ^ (s & 7u)));

    uint4 ua, ub;
    __half* A = (__half*)&ua;
    __half* B = (__half*)&ub;
#pragma unroll
    for (int e = 0; e < 8; e++) {
        __half a = __float2half_rn(x[e]);
        A[e] = a;
        B[e] = __float2half_rn(x[e] - __half2float(a));
    }
    if (which == 0)      { ((uint4*)g_Qa)[og] = ua; ((uint4*)g_Qb)[og] = ub; }
    else if (which == 1) { ((uint4*)g_Ka)[og] = ua; ((uint4*)g_Kb)[og] = ub; }
    else                 { ((uint4*)g_Vh)[og] = ua; }
}

// ---- prep: pack mask floats (0.0/1.0) into bits, 32 keys per uint32 ----
__global__ __launch_bounds__(256) void prep_mask(const float* __restrict__ M) {
    const uint32_t w = blockIdx.x * 256 + threadIdx.x;
    const float4* src = (const float4*)M + (size_t)w * 8;
    uint32_t bits = 0;
#pragma unroll
    for (int i = 0; i < 8; i++) {
        float4 v = src[i];
        bits |= (v.x != 0.0f ? 1u : 0u) << (4 * i + 0);
        bits |= (v.y != 0.0f ? 1u : 0u) << (4 * i + 1);
        bits |= (v.z != 0.0f ? 1u : 0u) << (4 * i + 2);
        bits |= (v.w != 0.0f ? 1u : 0u) << (4 * i + 3);
    }
    g_Mb[w] = bits;
}

// ---- main: 3 QK + 1 PV products, two-phase softmax, triple buffer, (128,3) ----
__global__ __launch_bounds__(128, 3)
void sdp_mma(float* __restrict__ Out) {
    extern __shared__ char smem[];
    const uint32_t sbase = smem_u32(smem);

    const int tid  = threadIdx.x;
    const int lane = tid & 31, warp = tid >> 5;
    const int bh = blockIdx.y, q0 = blockIdx.x * BM, b = bh >> 4;
    const int lq  = lane >> 2;
    const int lc2 = (lane & 3) * 2;
    const int r1 = q0 + warp * 16 + lq, r2 = r1 + 8;

    // Q fragments (2 splits), loaded once
    uint32_t qf[2][4][4];
    {
        const __half* qs[2] = {g_Qa, g_Qb};
#pragma unroll
        for (int sp = 0; sp < 2; sp++)
#pragma unroll
            for (int c = 0; c < 4; c++)
#pragma unroll
                for (int r = 0; r < 4; r++) {
                    int m = (r & 1) ? r2 : r1;
                    int k = c * 16 + ((r >> 1) << 3) + lc2;
                    qf[sp][c][r] = *(const uint32_t*)(qs[sp] + ((size_t)bh * Sv + m) * DKv + k);
                }
    }

    float O[8][4];
#pragma unroll
    for (int j = 0; j < 8; j++)
#pragma unroll
        for (int e = 0; e < 4; e++) O[j][e] = 0.0f;
    float lacc0 = 0.0f, lacc1 = 0.0f;

    const uint64_t* mb1 = (const uint64_t*)g_Mb + (((size_t)b * Sv + r1) << 5);
    const uint64_t* mb2 = (const uint64_t*)g_Mb + (((size_t)b * Sv + r2) << 5);

    const size_t gbyte0 = (size_t)(bh * Sv) * 128;
    const char* garr[3] = {(const char*)g_Ka + gbyte0, (const char*)g_Kb + gbyte0,
                           (const char*)g_Vh + gbyte0};

    // prologue: tiles 0 and 1 into buffers 0 and 1
#pragma unroll
    for (int a = 0; a < 3; a++)
#pragma unroll
        for (int i = 0; i < 4; i++) {
            uint32_t off = (uint32_t)(tid + i * 128) * 16;
            CPA(sbase + a * 8192 + off, garr[a] + off);
        }
    asm volatile("cp.async.commit_group;" ::: "memory");
#pragma unroll
    for (int a = 0; a < 3; a++)
#pragma unroll
        for (int i = 0; i < 4; i++) {
            uint32_t off = (uint32_t)(tid + i * 128) * 16;
            CPA(sbase + 24576 + a * 8192 + off, garr[a] + 8192 + off);
        }
    asm volatile("cp.async.commit_group;" ::: "memory");

    const int rowk = lane & 7;
    const int half = (lane >> 3) & 1;
    const uint32_t karr = (uint32_t)(lane >> 4) * 8192;
    const int rowv16 = lane & 15;
    const uint32_t jsel = (uint32_t)(lane >> 4);

    int cur = 0, pf = 2;
    for (int t = 0; t < NITER; t++) {
        // mask words early; their L2 latency hides under the QK MMAs
        const uint64_t s1 = mb1[t] >> lc2;
        const uint64_t s2 = mb2[t] >> lc2;

        if (t == NITER - 1) asm volatile("cp.async.wait_group 0;" ::: "memory");
        else                asm volatile("cp.async.wait_group 1;" ::: "memory");
        __syncthreads();   // tile t ready; all warps done with the buffer being refilled

        if (t + 2 < NITER) {
            const uint32_t sb = sbase + pf * 24576;
            const size_t go = (size_t)(t + 2) * 8192;
#pragma unroll
            for (int a = 0; a < 3; a++)
#pragma unroll
                for (int i = 0; i < 4; i++) {
                    uint32_t off = (uint32_t)(tid + i * 128) * 16;
                    CPA(sb + a * 8192 + off, garr[a] + go + off);
                }
            asm volatile("cp.async.commit_group;" ::: "memory");
        }

        const uint32_t sK = sbase + cur * 24576;   // Ka @ +0, Kb @ +8192
        const uint32_t sV = sK + 16384;            // Vh

        // two halves of 32 keys each: QK -> softmax -> PV per half.
        // PV of half 0 (tensor) overlaps softmax/ex2 of half 1 across the scheduler.
#pragma unroll
        for (int h = 0; h < 2; h++) {
            // ---- S over this half (3 split products) ----
            float S[4][4];
#pragma unroll
            for (int f = 0; f < 4; f++)
#pragma unroll
                for (int e = 0; e < 4; e++) S[f][e] = 0.0f;

#pragma unroll
            for (int c = 0; c < 4; c++) {
                const int chk = 2 * c + half;
#pragma unroll
                for (int f = 0; f < 4; f++) {
                    const int row = 8 * (4 * h + f) + rowk;
                    const uint32_t off = karr + (uint32_t)row * 128 + (uint32_t)((chk ^ (row & 7)) << 4);
                    uint32_t ka0, ka1, kb0, kb1;
                    ldsm4(ka0, ka1, kb0, kb1, sK + off);
                    mma16816(S[f], qf[0][c], ka0, ka1);   // Qa*Ka
                    mma16816(S[f], qf[1][c], ka0, ka1);   // Qb*Ka
                    mma16816(S[f], qf[0][c], kb0, kb1);   // Qa*Kb
                }
            }

            // ---- masked softmax via bit tests + MUFU ex2 ----
            uint32_t aph[4][2];
#pragma unroll
            for (int f = 0; f < 4; f++) {
                const unsigned w1 = (unsigned)(s1 >> (32 * h + 8 * f));
                const unsigned w2 = (unsigned)(s2 >> (32 * h + 8 * f));
                float p0 = pexpb(S[f][0], w1 & 1u);
                float p1 = pexpb(S[f][1], w1 & 2u);
                float p2 = pexpb(S[f][2], w2 & 1u);
                float p3 = pexpb(S[f][3], w2 & 2u);
                lacc0 += p0 + p1;
                lacc1 += p2 + p3;
                aph[f][0] = pack_h(p1, p0);
                aph[f][1] = pack_h(p3, p2);
            }

            // ---- O += P V over this half's 32 V-rows ----
#pragma unroll
            for (int cp = 0; cp < 2; cp++) {
                uint32_t a_h[4] = {aph[2 * cp][0], aph[2 * cp][1],
                                   aph[2 * cp + 1][0], aph[2 * cp + 1][1]};
                const int rowv = 32 * h + 16 * cp + rowv16;
#pragma unroll
                for (int jj = 0; jj < 4; jj++) {
                    const uint32_t j0 = 2 * jj;
                    const uint32_t offv = (uint32_t)rowv * 128 + (uint32_t)(((j0 + jsel) ^ (rowv & 7)) << 4);
                    uint32_t v00, v01, v10, v11;
                    ldsm4t(v00, v01, v10, v11, sV + offv);
                    mma16816(O[j0],     a_h, v00, v01);
                    mma16816(O[j0 + 1], a_h, v10, v11);
                }
            }
        }

        cur = (cur == 2) ? 0 : cur + 1;
        pf  = (pf  == 2) ? 0 : pf  + 1;
    }

    // ---- epilogue ----
    lacc0 += __shfl_xor_sync(0xffffffffu, lacc0, 1);
    lacc0 += __shfl_xor_sync(0xffffffffu, lacc0, 2);
    lacc1 += __shfl_xor_sync(0xffffffffu, lacc1, 1);
    lacc1 += __shfl_xor_sync(0xffffffffu, lacc1, 2);
    const float li1 = 1.0f / lacc0;
    const float li2 = 1.0f / lacc1;

    float* o1 = Out + ((size_t)bh * Sv + r1) * DKv + lc2;
    float* o2 = Out + ((size_t)bh * Sv + r2) * DKv + lc2;
#pragma unroll
    for (int j = 0; j < 8; j++) {
        float2 w1 = make_float2(O[j][0] * li1, O[j][1] * li1);
        float2 w2 = make_float2(O[j][2] * li2, O[j][3] * li2);
        *(float2*)(o1 + 8 * j) = w1;
        *(float2*)(o2 + 8 * j) = w2;
    }
}

extern "C" void kernel_launch(void* const* d_in, const int* in_sizes, int n_in,
                              void* d_out, int out_size) {
    const float* Q = (const float*)d_in[0];
    const float* K = (const float*)d_in[1];
    const float* V = (const float*)d_in[2];
    const float* M = (const float*)d_in[3];
    float* Out = (float*)d_out;

    prep<<<dim3((unsigned)(NELEM / 8 / 256), 3), 256>>>(Q, K, V);
    prep_mask<<<(unsigned)(NMASKW / 256), 256>>>(M);

    cudaFuncSetAttribute(sdp_mma, cudaFuncAttributeMaxDynamicSharedMemorySize, 73728);
    sdp_mma<<<dim3(Sv / BM, BHv), 128, 73728>>>(Out);
}